// round 16
// baseline (speedup 1.0000x reference)
#include <cuda_runtime.h>
#include <cuda_bf16.h>
#include <math.h>

#define B_  64
#define T_  1024
#define VOCAB_ 10000

typedef unsigned long long ull;

// ---- static scratch (no allocations allowed) ----
__device__ ulonglong2 g_xg2[B_ * T_ * 32];   // 33.5 MB : packed (i,f),(g,o), pre-scaled
__device__ float g_h [B_ * T_ * 32];         //  8.4 MB : LSTM hidden states
__device__ float g_pacc[B_ * 2 * T_ * 32];   // 16.8 MB : unnormalized ctx partials per s-chunk
__device__ float g_pz [B_ * 2 * T_];         //  0.5 MB : partial softmax sums per s-chunk

#define LOG2E 1.4426950408889634f

// ---- helpers ----
__device__ __forceinline__ float ex2f(float x) {
    float r; asm("ex2.approx.f32 %0, %1;" : "=f"(r) : "f"(x)); return r;
}
__device__ __forceinline__ float rcpf(float x) {
    float r; asm("rcp.approx.f32 %0, %1;" : "=f"(r) : "f"(x)); return r;
}
__device__ __forceinline__ ull pk(float a, float b) {
    ull r; asm("mov.b64 %0, {%1, %2};" : "=l"(r) : "f"(a), "f"(b)); return r;
}
__device__ __forceinline__ void upk(ull v, float& a, float& b) {
    asm("mov.b64 {%0, %1}, %2;" : "=f"(a), "=f"(b) : "l"(v));
}
__device__ __forceinline__ ull ffma2(ull a, ull b, ull c) {
    ull r; asm("fma.rn.f32x2 %0, %1, %2, %3;" : "=l"(r) : "l"(a), "l"(b), "l"(c)); return r;
}
__device__ __forceinline__ ull add2(ull a, ull b) {
    ull r; asm("add.rn.f32x2 %0, %1, %2;" : "=l"(r) : "l"(a), "l"(b)); return r;
}

// ============================================================
// Kernel 1: zero-token index queue (last 100 zeros, ascending, -1 padded front)
// ============================================================
__global__ void queue_kernel(const int* __restrict__ in, float* __restrict__ out,
                             int out_size) {
    if (out_size < 2248) return;
    float* q = out + (out_size - 200);
    int tid = threadIdx.x;                 // 0..1023
    int base = tid * 64;
    ull m = 0;
    const int4* p4 = (const int4*)(in + base);
#pragma unroll
    for (int k = 0; k < 16; k++) {
        int4 v = p4[k];
        if (v.x == 0 || v.x >= VOCAB_) m |= 1ull << (4 * k + 0);
        if (v.y == 0 || v.y >= VOCAB_) m |= 1ull << (4 * k + 1);
        if (v.z == 0 || v.z >= VOCAB_) m |= 1ull << (4 * k + 2);
        if (v.w == 0 || v.w >= VOCAB_) m |= 1ull << (4 * k + 3);
    }
    int cnt = __popcll(m);
    int lane = tid & 31, wid = tid >> 5;
    int v = cnt;
#pragma unroll
    for (int o = 1; o < 32; o <<= 1) {
        int t = __shfl_up_sync(0xffffffffu, v, o);
        if (lane >= o) v += t;
    }
    __shared__ int wsum[32];
    __shared__ int woff[32];
    __shared__ int stot;
    if (lane == 31) wsum[wid] = v;
    __syncthreads();
    if (wid == 0) {
        int x = wsum[lane];
        int y = x;
#pragma unroll
        for (int o = 1; o < 32; o <<= 1) {
            int t = __shfl_up_sync(0xffffffffu, y, o);
            if (lane >= o) y += t;
        }
        woff[lane] = y - x;
        if (lane == 31) stot = y;
    }
    __syncthreads();
    int total = stot;
    int excl = woff[wid] + v - cnt;
    if (tid < 200) q[tid] = -1.0f;
    __syncthreads();
    int r = excl;
    ull mm = m;
    while (mm) {
        int k = __ffsll(mm) - 1;
        mm &= mm - 1;
        int slot = r - total + 100;
        if (slot >= 0) {
            int p = base + k;
            q[slot * 2]     = (float)(p >> 10);
            q[slot * 2 + 1] = (float)(p & 1023);
        }
        r++;
    }
}

// ============================================================
// Kernel 2: xg = b_lstm + emb[id]@k, packed (i,f),(g,o), PRE-SCALED:
// i,f,o gates by -log2e (sigmoid via ex2), g gate by 2*log2e (tanh via ex2).
// ============================================================
__global__ __launch_bounds__(256) void xg_kernel(const int* __restrict__ inp,
                                                 const float* __restrict__ emb,
                                                 const float* __restrict__ klstm,
                                                 const float* __restrict__ blstm) {
    int b  = blockIdx.x >> 3;
    int tb = (blockIdx.x & 7) * 128;
    int tid = threadIdx.x, lane = tid & 31, w = tid >> 5;
    float kr[4][32];
#pragma unroll
    for (int d = 0; d < 32; d++)
#pragma unroll
        for (int qq = 0; qq < 4; qq++) kr[qq][d] = klstm[d * 128 + qq * 32 + lane];
    float br[4];
#pragma unroll
    for (int qq = 0; qq < 4; qq++) br[qq] = blstm[qq * 32 + lane];

    for (int i = 0; i < 16; i++) {
        int t = tb + w * 16 + i;
        int u = inp[b * T_ + t];
        int id = (u < VOCAB_) ? u : 0;
        float ev = emb[id * 32 + lane];
        float a0 = br[0], a1 = br[1], a2 = br[2], a3 = br[3];
#pragma unroll
        for (int d = 0; d < 32; d++) {
            float e = __shfl_sync(0xffffffffu, ev, d);
            a0 = fmaf(e, kr[0][d], a0);
            a1 = fmaf(e, kr[1][d], a1);
            a2 = fmaf(e, kr[2][d], a2);
            a3 = fmaf(e, kr[3][d], a3);
        }
        ulonglong2 vv;
        vv.x = pk(a0 * (-LOG2E), a1 * (-LOG2E));       // (i, f)
        vv.y = pk(a2 * (2.0f * LOG2E), a3 * (-LOG2E)); // (g, o)
        g_xg2[(b * T_ + t) * 32 + lane] = vv;
    }
}

// ============================================================
// Kernel 3: LSTM recurrence. 32 blocks x 1 warp; each warp interleaves TWO
// independent batches (shared rk registers) so batch B's issue fills batch
// A's latency shadows. Thread = unit, packed f32x2 gates, zero barriers.
// ============================================================
__global__ __launch_bounds__(32, 1) void lstm_kernel(const float* __restrict__ rk) {
    int bA = blockIdx.x * 2, bB = bA + 1;
    int lane = threadIdx.x;
    const float FOUR_L = 4.0f * LOG2E, TWO_L = 2.0f * LOG2E;
    ull rkif[32], rkgo[32];
#pragma unroll
    for (int d = 0; d < 32; d++) {
        const float* rr = rk + d * 128;
        rkif[d] = pk(rr[lane] * (-LOG2E),      rr[32 + lane] * (-LOG2E));
        rkgo[d] = pk(rr[64 + lane] * TWO_L,    rr[96 + lane] * (-LOG2E));
    }
    __shared__ ull h2A[2][32], h2B[2][32];   // duplicated (h,h), double-buffered
    h2A[0][lane] = pk(0.f, 0.f);
    h2B[0][lane] = pk(0.f, 0.f);
    float cA = 0.f, cB = 0.f;                // c pre-scaled by 2*log2e
    float* hbA = g_h + bA * T_ * 32;
    float* hbB = g_h + bB * T_ * 32;
    const ulonglong2* xgA = g_xg2 + bA * T_ * 32;
    const ulonglong2* xgB = g_xg2 + bB * T_ * 32;
    ulonglong2 xqA0 = xgA[lane],        xqB0 = xgB[lane];
    ulonglong2 xqA1 = xgA[32 + lane],   xqB1 = xgB[32 + lane];
    ulonglong2 xqA2 = xgA[64 + lane],   xqB2 = xgB[64 + lane];
    ulonglong2 xqA3 = xgA[96 + lane],   xqB3 = xgB[96 + lane];
    __syncwarp();
    const ull z64 = pk(0.f, 0.f);

#define PAIR_STEP(XA, XB, TT)                                                 \
    {                                                                         \
        ull xifA = (XA).x, xifB = (XB).x;                                     \
        ull goA1 = (XA).y, goA2 = z64, goB1 = (XB).y, goB2 = z64;             \
        const ulonglong2* hvA = (const ulonglong2*)h2A[(TT) & 1];             \
        const ulonglong2* hvB = (const ulonglong2*)h2B[(TT) & 1];             \
        if ((TT) + 4 < T_) {                                                  \
            XA = xgA[((TT) + 4) * 32 + lane];                                 \
            XB = xgB[((TT) + 4) * 32 + lane];                                 \
        }                                                                     \
        _Pragma("unroll")                                                     \
        for (int j = 0; j < 8; j++) {                                         \
            ulonglong2 va = hvA[j];                                           \
            goA1 = ffma2(va.x, rkgo[2 * j],     goA1);                        \
            goA2 = ffma2(va.y, rkgo[2 * j + 1], goA2);                        \
        }                                                                     \
        _Pragma("unroll")                                                     \
        for (int j = 0; j < 8; j++) {                                         \
            ulonglong2 vb = hvB[j];                                           \
            goB1 = ffma2(vb.x, rkgo[2 * j],     goB1);                        \
            goB2 = ffma2(vb.y, rkgo[2 * j + 1], goB2);                        \
        }                                                                     \
        float zgA, zoA, zgB, zoB;                                             \
        upk(add2(goA1, goA2), zgA, zoA);                                      \
        upk(add2(goB1, goB2), zgB, zoB);                                      \
        float agA = fmaf(-FOUR_L, rcpf(ex2f(zgA) + 1.f), TWO_L);              \
        float aoA = rcpf(1.f + ex2f(zoA));                                    \
        float agB = fmaf(-FOUR_L, rcpf(ex2f(zgB) + 1.f), TWO_L);              \
        float aoB = rcpf(1.f + ex2f(zoB));                                    \
        ull ifA1 = xifA, ifA2 = z64, ifB1 = xifB, ifB2 = z64;                 \
        _Pragma("unroll")                                                     \
        for (int j = 0; j < 8; j++) {                                         \
            ulonglong2 va = hvA[j];                                           \
            ifA1 = ffma2(va.x, rkif[2 * j],     ifA1);                        \
            ifA2 = ffma2(va.y, rkif[2 * j + 1], ifA2);                        \
        }                                                                     \
        _Pragma("unroll")                                                     \
        for (int j = 0; j < 8; j++) {                                         \
            ulonglong2 vb = hvB[j];                                           \
            ifB1 = ffma2(vb.x, rkif[2 * j],     ifB1);                        \
            ifB2 = ffma2(vb.y, rkif[2 * j + 1], ifB2);                        \
        }                                                                     \
        float ziA, zfA, ziB, zfB;                                             \
        upk(add2(ifA1, ifA2), ziA, zfA);                                      \
        upk(add2(ifB1, ifB2), ziB, zfB);                                      \
        float aiA = rcpf(1.f + ex2f(ziA));                                    \
        float afA = rcpf(1.f + ex2f(zfA));                                    \
        float aiB = rcpf(1.f + ex2f(ziB));                                    \
        float afB = rcpf(1.f + ex2f(zfB));                                    \
        cA = fmaf(afA, cA, aiA * agA);                                        \
        cB = fmaf(afB, cB, aiB * agB);                                        \
        float hA = aoA * fmaf(-2.f, rcpf(ex2f(cA) + 1.f), 1.f);               \
        float hB = aoB * fmaf(-2.f, rcpf(ex2f(cB) + 1.f), 1.f);               \
        hbA[(TT) * 32 + lane] = hA;                                           \
        hbB[(TT) * 32 + lane] = hB;                                           \
        h2A[((TT) & 1) ^ 1][lane] = pk(hA, hA);                               \
        h2B[((TT) & 1) ^ 1][lane] = pk(hB, hB);                               \
        __syncwarp();                                                         \
    }

    for (int t = 0; t < T_; t += 4) {
        PAIR_STEP(xqA0, xqB0, t);
        PAIR_STEP(xqA1, xqB1, t + 1);
        PAIR_STEP(xqA2, xqB2, t + 2);
        PAIR_STEP(xqA3, xqB3, t + 3);
    }
#undef PAIR_STEP
}

// ============================================================
// Kernel 4: attention partials (best measured config).
// grid (16, 64): row-tile(8) x chunk(2) x b. 128 threads, 1 row/thread,
// 3 blocks/SM. ht pre-scaled by log2e -> p = ex2(dot). Partials to gmem.
// ============================================================
#define ATTN_SMEM (512 * 32 * 4)
__global__ __launch_bounds__(128, 3) void attn_kernel() {
    extern __shared__ float hs[];
    int tile = blockIdx.x >> 1, cid = blockIdx.x & 1;
    int b = blockIdx.y;
    int tid = threadIdx.x;
    const float* hbase = g_h + b * (T_ * 32);
    {   // stage this chunk's 512 keys (64KB)
        const float4* src = (const float4*)(hbase + cid * 512 * 32);
        float4* dst = (float4*)hs;
        for (int i = tid; i < 4096; i += 128) dst[i] = src[i];
    }
    int r = tile * 128 + tid;
    ull ht[16];
    {
        const float4* hr = (const float4*)(hbase + r * 32);
#pragma unroll
        for (int j = 0; j < 8; j++) {
            float4 a = hr[j];
            ht[2 * j]     = pk(a.x * LOG2E, a.y * LOG2E);
            ht[2 * j + 1] = pk(a.z * LOG2E, a.w * LOG2E);
        }
    }
    __syncthreads();
    const ull z64 = pk(0.f, 0.f);
    ull acc[16];
#pragma unroll
    for (int k = 0; k < 16; k++) acc[k] = z64;
    float Z = 0.f;

    for (int s = 0; s < 512; s++) {
        const ulonglong2* hv = (const ulonglong2*)(hs + s * 32);  // uniform -> broadcast
        ull hp[16];
#pragma unroll
        for (int j = 0; j < 8; j++) {
            ulonglong2 v = hv[j];
            hp[2 * j] = v.x; hp[2 * j + 1] = v.y;
        }
        ull d1 = ffma2(hp[0], ht[0], z64);
        ull d2 = ffma2(hp[1], ht[1], z64);
#pragma unroll
        for (int k = 2; k < 16; k += 2) {
            d1 = ffma2(hp[k],     ht[k],     d1);
            d2 = ffma2(hp[k + 1], ht[k + 1], d2);
        }
        float a, bb;
        upk(add2(d1, d2), a, bb);
        float p = ex2f(a + bb);            // dot pre-scaled by log2e
        Z += p;
        ull pp = pk(p, p);
#pragma unroll
        for (int k = 0; k < 16; k++) acc[k] = ffma2(pp, hp[k], acc[k]);
    }
    int orow = (b * 2 + cid) * T_ + r;
    g_pz[orow] = Z;
    float4* po = (float4*)(g_pacc + (size_t)orow * 32);
#pragma unroll
    for (int k = 0; k < 8; k++) {
        float x0, y0, x1, y1;
        upk(acc[2 * k],     x0, y0);
        upk(acc[2 * k + 1], x1, y1);
        po[k] = make_float4(x0, y0, x1, y1);
    }
}

// ============================================================
// Kernel 5: combine partials -> ctx -> y = ctx^T h -> MLP -> out. grid 64.
// ============================================================
__global__ __launch_bounds__(256) void combine_final(const float* __restrict__ W1,
                                                     const float* __restrict__ b1,
                                                     const float* __restrict__ W2,
                                                     const float* __restrict__ b2,
                                                     float* __restrict__ out) {
    __shared__ float sctx[128 * 36];   // padded stride 36 (16B-aligned rows)
    __shared__ float sh[128 * 32];
    int b = blockIdx.x, tid = threadIdx.x;
    int dd = tid >> 3, ee = (tid & 7) * 4;
    float4 y4 = make_float4(0.f, 0.f, 0.f, 0.f);
    const float* pz0 = g_pz + (b * 2) * T_;
    const float* pz1 = g_pz + (b * 2 + 1) * T_;

    for (int tb = 0; tb < 8; tb++) {
        {   // stage ctx: 2 threads per t (halves of 16 dims)
            int t = tb * 128 + (tid >> 1);
            int half = (tid & 1) * 16;
            float inv = 1.f / (pz0[t] + pz1[t]);
            const float4* pa0 = (const float4*)(g_pacc + ((size_t)(b * 2) * T_ + t) * 32 + half);
            const float4* pa1 = (const float4*)(g_pacc + ((size_t)(b * 2 + 1) * T_ + t) * 32 + half);
            float4* so = (float4*)(sctx + (tid >> 1) * 36 + half);
#pragma unroll
            for (int q = 0; q < 4; q++) {
                float4 u = pa0[q], v = pa1[q];
                so[q] = make_float4((u.x + v.x) * inv, (u.y + v.y) * inv,
                                    (u.z + v.z) * inv, (u.w + v.w) * inv);
            }
        }
        {   // stage h tile
            const float4* hsrc = (const float4*)(g_h + b * (T_ * 32) + tb * 128 * 32);
            float4* hdst = (float4*)sh;
#pragma unroll
            for (int q = 0; q < 4; q++) hdst[tid + 256 * q] = hsrc[tid + 256 * q];
        }
        __syncthreads();
        for (int t2 = 0; t2 < 128; t2++) {
            float cv = sctx[t2 * 36 + dd];
            float4 hv = *(const float4*)(sh + t2 * 32 + ee);
            y4.x = fmaf(cv, hv.x, y4.x);
            y4.y = fmaf(cv, hv.y, y4.y);
            y4.z = fmaf(cv, hv.z, y4.z);
            y4.w = fmaf(cv, hv.w, y4.w);
        }
        __syncthreads();
    }
    // y -> smem (reuse sctx as flat [32][32])
    float* ysh = sctx;
    *(float4*)(ysh + dd * 32 + ee) = y4;
    __syncthreads();
    if (tid < 32) {
        int d = tid;
        float acc = b2[0];
        for (int e = 0; e < 32; e++) {
            float s = b1[e];
#pragma unroll
            for (int kk = 0; kk < 32; kk++)
                s = fmaf(ysh[d * 32 + kk], W1[kk * 32 + e], s);
            s = fmaxf(s, 0.f);
            acc = fmaf(s, W2[e], acc);
        }
        out[b * 32 + d] = 1.0f / (1.0f + __expf(-acc));
    }
}

// ============================================================
extern "C" void kernel_launch(void* const* d_in, const int* in_sizes, int n_in,
                              void* d_out, int out_size) {
    const int*   inputs = (const int*)  d_in[0];
    const float* emb    = (const float*)d_in[1];
    const float* klstm  = (const float*)d_in[2];
    const float* rklstm = (const float*)d_in[3];
    const float* blstm  = (const float*)d_in[4];
    const float* W1     = (const float*)d_in[5];
    const float* b1     = (const float*)d_in[6];
    const float* W2     = (const float*)d_in[7];
    const float* b2     = (const float*)d_in[8];
    float* out = (float*)d_out;

    cudaFuncSetAttribute(attn_kernel, cudaFuncAttributeMaxDynamicSharedMemorySize,
                         ATTN_SMEM);

    queue_kernel<<<1, 1024>>>(inputs, out, out_size);
    xg_kernel<<<512, 256>>>(inputs, emb, klstm, blstm);
    lstm_kernel<<<32, 32>>>(rklstm);
    attn_kernel<<<dim3(16, 64), 128, ATTN_SMEM>>>();
    combine_final<<<64, 256>>>(W1, b1, W2, b2, out);
}

// round 17
// speedup vs baseline: 1.1521x; 1.1521x over previous
#include <cuda_runtime.h>
#include <cuda_bf16.h>
#include <math.h>

#define B_  64
#define T_  1024
#define VOCAB_ 10000

typedef unsigned long long ull;

// ---- static scratch (no allocations allowed) ----
__device__ float g_xkf[VOCAB_ * 128];        //  5.1 MB : per-vocab prescaled gate table (L2-resident)
__device__ float g_h [B_ * T_ * 32];         //  8.4 MB : LSTM hidden states
__device__ float g_pacc[B_ * 2 * T_ * 32];   // 16.8 MB : unnormalized ctx partials per s-chunk
__device__ float g_pz [B_ * 2 * T_];         //  0.5 MB : partial softmax sums per s-chunk

#define LOG2E 1.4426950408889634f

// ---- helpers ----
__device__ __forceinline__ float ex2f(float x) {
    float r; asm("ex2.approx.f32 %0, %1;" : "=f"(r) : "f"(x)); return r;
}
__device__ __forceinline__ float rcpf(float x) {
    float r; asm("rcp.approx.f32 %0, %1;" : "=f"(r) : "f"(x)); return r;
}
__device__ __forceinline__ ull pk(float a, float b) {
    ull r; asm("mov.b64 %0, {%1, %2};" : "=l"(r) : "f"(a), "f"(b)); return r;
}
__device__ __forceinline__ void upk(ull v, float& a, float& b) {
    asm("mov.b64 {%0, %1}, %2;" : "=f"(a), "=f"(b) : "l"(v));
}
__device__ __forceinline__ ull ffma2(ull a, ull b, ull c) {
    ull r; asm("fma.rn.f32x2 %0, %1, %2, %3;" : "=l"(r) : "l"(a), "l"(b), "l"(c)); return r;
}
__device__ __forceinline__ ull add2(ull a, ull b) {
    ull r; asm("add.rn.f32x2 %0, %1, %2;" : "=l"(r) : "l"(a), "l"(b)); return r;
}

// ============================================================
// Kernel 1: zero-token index queue (last 100 zeros, ascending, -1 padded front)
// ============================================================
__global__ void queue_kernel(const int* __restrict__ in, float* __restrict__ out,
                             int out_size) {
    if (out_size < 2248) return;
    float* q = out + (out_size - 200);
    int tid = threadIdx.x;                 // 0..1023
    int base = tid * 64;
    ull m = 0;
    const int4* p4 = (const int4*)(in + base);
#pragma unroll
    for (int k = 0; k < 16; k++) {
        int4 v = p4[k];
        if (v.x == 0 || v.x >= VOCAB_) m |= 1ull << (4 * k + 0);
        if (v.y == 0 || v.y >= VOCAB_) m |= 1ull << (4 * k + 1);
        if (v.z == 0 || v.z >= VOCAB_) m |= 1ull << (4 * k + 2);
        if (v.w == 0 || v.w >= VOCAB_) m |= 1ull << (4 * k + 3);
    }
    int cnt = __popcll(m);
    int lane = tid & 31, wid = tid >> 5;
    int v = cnt;
#pragma unroll
    for (int o = 1; o < 32; o <<= 1) {
        int t = __shfl_up_sync(0xffffffffu, v, o);
        if (lane >= o) v += t;
    }
    __shared__ int wsum[32];
    __shared__ int woff[32];
    __shared__ int stot;
    if (lane == 31) wsum[wid] = v;
    __syncthreads();
    if (wid == 0) {
        int x = wsum[lane];
        int y = x;
#pragma unroll
        for (int o = 1; o < 32; o <<= 1) {
            int t = __shfl_up_sync(0xffffffffu, y, o);
            if (lane >= o) y += t;
        }
        woff[lane] = y - x;
        if (lane == 31) stot = y;
    }
    __syncthreads();
    int total = stot;
    int excl = woff[wid] + v - cnt;
    if (tid < 200) q[tid] = -1.0f;
    __syncthreads();
    int r = excl;
    ull mm = m;
    while (mm) {
        int k = __ffsll(mm) - 1;
        mm &= mm - 1;
        int slot = r - total + 100;
        if (slot >= 0) {
            int p = base + k;
            q[slot * 2]     = (float)(p >> 10);
            q[slot * 2 + 1] = (float)(p & 1023);
        }
        r++;
    }
}

// ============================================================
// Kernel 2: vocab gate table. xkf[v][g] = prescale_g * (b[g] + emb[v]@k[:,g]).
// Grid 1250 x 256: warp = vocab row (1250*8 = 10000 exactly). k staged in smem.
// Same accumulation order as the old per-token xg -> identical numerics.
// ============================================================
__global__ __launch_bounds__(256) void xk_kernel(const float* __restrict__ emb,
                                                 const float* __restrict__ klstm,
                                                 const float* __restrict__ blstm) {
    __shared__ float sk[4096];   // k[32][128]
    int tid = threadIdx.x, lane = tid & 31, w = tid >> 5;
    for (int i = tid; i < 4096; i += 256) sk[i] = klstm[i];
    __syncthreads();
    int row = blockIdx.x * 8 + w;
    float ev = emb[row * 32 + lane];
    float a0 = blstm[lane];
    float a1 = blstm[32 + lane];
    float a2 = blstm[64 + lane];
    float a3 = blstm[96 + lane];
#pragma unroll
    for (int d = 0; d < 32; d++) {
        float e = __shfl_sync(0xffffffffu, ev, d);
        a0 = fmaf(e, sk[d * 128 + lane],      a0);
        a1 = fmaf(e, sk[d * 128 + 32 + lane], a1);
        a2 = fmaf(e, sk[d * 128 + 64 + lane], a2);
        a3 = fmaf(e, sk[d * 128 + 96 + lane], a3);
    }
    float* o = g_xkf + row * 128;
    o[lane]      = a0 * (-LOG2E);        // i
    o[32 + lane] = a1 * (-LOG2E);        // f
    o[64 + lane] = a2 * (2.0f * LOG2E);  // g
    o[96 + lane] = a3 * (-LOG2E);        // o
}

// ============================================================
// Kernel 3: LSTM recurrence (R11 config — best measured).
// 64 blocks x 128 threads, warp = gate, lane = unit. x gathered directly
// from the vocab table by token id (two-level prefetch ring: ids at
// distance 8, x at distance 4; table is L2-resident).
// ============================================================
__global__ __launch_bounds__(128, 1) void lstm_kernel(const float* __restrict__ rk,
                                                      const int* __restrict__ inp) {
    int b = blockIdx.x;
    int tid = threadIdx.x;
    int lane = tid & 31, w = tid >> 5;         // w = gate
    const float FOUR_L = 4.0f * LOG2E, TWO_L = 2.0f * LOG2E;
    float scale = (w == 2) ? TWO_L : (-LOG2E);
    ull rkp[16];
#pragma unroll
    for (int j = 0; j < 16; j++) {
        rkp[j] = pk(rk[(2 * j) * 128 + w * 32 + lane] * scale,
                    rk[(2 * j + 1) * 128 + w * 32 + lane] * scale);
    }
    __shared__ ull hsh[16];          // packed (h[2j], h[2j+1])
    __shared__ float acts[128];
    if (tid < 16) hsh[tid] = pk(0.f, 0.f);
    float c2 = 0.f;                  // c pre-scaled by 2*log2e
    float* hb = g_h + b * T_ * 32;
    const int* ib = inp + b * T_;
    int goff = w * 32 + lane;
    const float* xk = g_xkf + goff;
    // x ring (distance 4) + id ring (distance 8)
    int u;
    u = ib[0]; float xq0 = xk[((u < VOCAB_) ? u : 0) * 128];
    u = ib[1]; float xq1 = xk[((u < VOCAB_) ? u : 0) * 128];
    u = ib[2]; float xq2 = xk[((u < VOCAB_) ? u : 0) * 128];
    u = ib[3]; float xq3 = xk[((u < VOCAB_) ? u : 0) * 128];
    u = ib[4]; int id0 = (u < VOCAB_) ? u : 0;
    u = ib[5]; int id1 = (u < VOCAB_) ? u : 0;
    u = ib[6]; int id2 = (u < VOCAB_) ? u : 0;
    u = ib[7]; int id3 = (u < VOCAB_) ? u : 0;
    __syncthreads();
    const ull z64 = pk(0.f, 0.f);

#define LSTM_STEP(XQ, IDQ, TT)                                                \
    {                                                                         \
        ull za = pk(XQ, 0.f), zb = z64;                                       \
        if ((TT) + 4 < T_) XQ = xk[(IDQ) * 128];                              \
        if ((TT) + 8 < T_) {                                                  \
            int uu = ib[(TT) + 8];                                            \
            IDQ = (uu < VOCAB_) ? uu : 0;                                     \
        }                                                                     \
        const ulonglong2* hv = (const ulonglong2*)hsh;                        \
        _Pragma("unroll")                                                     \
        for (int j = 0; j < 8; j++) {                                         \
            ulonglong2 vv = hv[j];                                            \
            za = ffma2(vv.x, rkp[2 * j],     za);                             \
            zb = ffma2(vv.y, rkp[2 * j + 1], zb);                             \
        }                                                                     \
        float zl, zh;                                                         \
        upk(add2(za, zb), zl, zh);                                            \
        float z = zl + zh;                                                    \
        float a;                                                              \
        if (w == 2) a = fmaf(-FOUR_L, rcpf(ex2f(z) + 1.f), TWO_L);            \
        else        a = rcpf(1.f + ex2f(z));                                  \
        acts[w * 32 + lane] = a;                                              \
        __syncthreads();                                                      \
        if (w == 0) {                                                         \
            float ai = a;                                                     \
            float af  = acts[32 + lane];                                      \
            float ag2 = acts[64 + lane];                                      \
            float ao  = acts[96 + lane];                                      \
            c2 = fmaf(af, c2, ai * ag2);                                      \
            float h = ao * fmaf(-2.f, rcpf(ex2f(c2) + 1.f), 1.f);             \
            hb[(TT) * 32 + lane] = h;                                         \
            int j2 = lane & 15;                                               \
            float he = __shfl_sync(0xffffffffu, h, 2 * j2);                   \
            float ho = __shfl_sync(0xffffffffu, h, 2 * j2 + 1);               \
            if (lane < 16) hsh[lane] = pk(he, ho);                            \
        }                                                                     \
        __syncthreads();                                                      \
    }

    for (int t = 0; t < T_; t += 4) {
        LSTM_STEP(xq0, id0, t);
        LSTM_STEP(xq1, id1, t + 1);
        LSTM_STEP(xq2, id2, t + 2);
        LSTM_STEP(xq3, id3, t + 3);
    }
#undef LSTM_STEP
}

// ============================================================
// Kernel 4: attention partials (best measured config, unchanged).
// grid (16, 64): row-tile(8) x chunk(2) x b. 128 threads, 1 row/thread,
// 3 blocks/SM. ht pre-scaled by log2e -> p = ex2(dot). Partials to gmem.
// ============================================================
#define ATTN_SMEM (512 * 32 * 4)
__global__ __launch_bounds__(128, 3) void attn_kernel() {
    extern __shared__ float hs[];
    int tile = blockIdx.x >> 1, cid = blockIdx.x & 1;
    int b = blockIdx.y;
    int tid = threadIdx.x;
    const float* hbase = g_h + b * (T_ * 32);
    {   // stage this chunk's 512 keys (64KB)
        const float4* src = (const float4*)(hbase + cid * 512 * 32);
        float4* dst = (float4*)hs;
        for (int i = tid; i < 4096; i += 128) dst[i] = src[i];
    }
    int r = tile * 128 + tid;
    ull ht[16];
    {
        const float4* hr = (const float4*)(hbase + r * 32);
#pragma unroll
        for (int j = 0; j < 8; j++) {
            float4 a = hr[j];
            ht[2 * j]     = pk(a.x * LOG2E, a.y * LOG2E);
            ht[2 * j + 1] = pk(a.z * LOG2E, a.w * LOG2E);
        }
    }
    __syncthreads();
    const ull z64 = pk(0.f, 0.f);
    ull acc[16];
#pragma unroll
    for (int k = 0; k < 16; k++) acc[k] = z64;
    float Z = 0.f;

    for (int s = 0; s < 512; s++) {
        const ulonglong2* hv = (const ulonglong2*)(hs + s * 32);  // uniform -> broadcast
        ull hp[16];
#pragma unroll
        for (int j = 0; j < 8; j++) {
            ulonglong2 v = hv[j];
            hp[2 * j] = v.x; hp[2 * j + 1] = v.y;
        }
        ull d1 = ffma2(hp[0], ht[0], z64);
        ull d2 = ffma2(hp[1], ht[1], z64);
#pragma unroll
        for (int k = 2; k < 16; k += 2) {
            d1 = ffma2(hp[k],     ht[k],     d1);
            d2 = ffma2(hp[k + 1], ht[k + 1], d2);
        }
        float a, bb;
        upk(add2(d1, d2), a, bb);
        float p = ex2f(a + bb);            // dot pre-scaled by log2e
        Z += p;
        ull pp = pk(p, p);
#pragma unroll
        for (int k = 0; k < 16; k++) acc[k] = ffma2(pp, hp[k], acc[k]);
    }
    int orow = (b * 2 + cid) * T_ + r;
    g_pz[orow] = Z;
    float4* po = (float4*)(g_pacc + (size_t)orow * 32);
#pragma unroll
    for (int k = 0; k < 8; k++) {
        float x0, y0, x1, y1;
        upk(acc[2 * k],     x0, y0);
        upk(acc[2 * k + 1], x1, y1);
        po[k] = make_float4(x0, y0, x1, y1);
    }
}

// ============================================================
// Kernel 5: combine partials -> ctx -> y = ctx^T h -> MLP -> out. grid 64.
// MLP tail parallelized: warp w handles rows d = 4w..4w+3, lane = e.
// ============================================================
__global__ __launch_bounds__(256) void combine_final(const float* __restrict__ W1,
                                                     const float* __restrict__ b1,
                                                     const float* __restrict__ W2,
                                                     const float* __restrict__ b2,
                                                     float* __restrict__ out) {
    __shared__ float sctx[128 * 36];   // padded stride 36 (16B-aligned rows)
    __shared__ float sh[128 * 32];
    int b = blockIdx.x, tid = threadIdx.x;
    int lane = tid & 31, w = tid >> 5;
    int dd = tid >> 3, ee = (tid & 7) * 4;
    float4 y4 = make_float4(0.f, 0.f, 0.f, 0.f);
    const float* pz0 = g_pz + (b * 2) * T_;
    const float* pz1 = g_pz + (b * 2 + 1) * T_;

    for (int tb = 0; tb < 8; tb++) {
        {   // stage ctx: 2 threads per t (halves of 16 dims)
            int t = tb * 128 + (tid >> 1);
            int half = (tid & 1) * 16;
            float inv = 1.f / (pz0[t] + pz1[t]);
            const float4* pa0 = (const float4*)(g_pacc + ((size_t)(b * 2) * T_ + t) * 32 + half);
            const float4* pa1 = (const float4*)(g_pacc + ((size_t)(b * 2 + 1) * T_ + t) * 32 + half);
            float4* so = (float4*)(sctx + (tid >> 1) * 36 + half);
#pragma unroll
            for (int q = 0; q < 4; q++) {
                float4 u = pa0[q], v = pa1[q];
                so[q] = make_float4((u.x + v.x) * inv, (u.y + v.y) * inv,
                                    (u.z + v.z) * inv, (u.w + v.w) * inv);
            }
        }
        {   // stage h tile
            const float4* hsrc = (const float4*)(g_h + b * (T_ * 32) + tb * 128 * 32);
            float4* hdst = (float4*)sh;
#pragma unroll
            for (int q = 0; q < 4; q++) hdst[tid + 256 * q] = hsrc[tid + 256 * q];
        }
        __syncthreads();
        for (int t2 = 0; t2 < 128; t2++) {
            float cv = sctx[t2 * 36 + dd];
            float4 hv = *(const float4*)(sh + t2 * 32 + ee);
            y4.x = fmaf(cv, hv.x, y4.x);
            y4.y = fmaf(cv, hv.y, y4.y);
            y4.z = fmaf(cv, hv.z, y4.z);
            y4.w = fmaf(cv, hv.w, y4.w);
        }
        __syncthreads();
    }
    // y -> smem (reuse sctx as flat [32][32])
    float* ysh = sctx;
    *(float4*)(ysh + dd * 32 + ee) = y4;
    __syncthreads();
    // MLP tail: warp w -> rows d = 4w..4w+3, lane = hidden unit e
    float w2e = W2[lane];
    float b1e = b1[lane];
#pragma unroll
    for (int q = 0; q < 4; q++) {
        int d = w * 4 + q;
        float s = b1e;
#pragma unroll
        for (int kk = 0; kk < 32; kk++)
            s = fmaf(ysh[d * 32 + kk], W1[kk * 32 + lane], s);
        s = fmaxf(s, 0.f);
        float part = s * w2e;
#pragma unroll
        for (int o = 16; o > 0; o >>= 1)
            part += __shfl_down_sync(0xffffffffu, part, o);
        if (lane == 0)
            out[b * 32 + d] = 1.0f / (1.0f + __expf(-(part + b2[0])));
    }
}

// ============================================================
extern "C" void kernel_launch(void* const* d_in, const int* in_sizes, int n_in,
                              void* d_out, int out_size) {
    const int*   inputs = (const int*)  d_in[0];
    const float* emb    = (const float*)d_in[1];
    const float* klstm  = (const float*)d_in[2];
    const float* rklstm = (const float*)d_in[3];
    const float* blstm  = (const float*)d_in[4];
    const float* W1     = (const float*)d_in[5];
    const float* b1     = (const float*)d_in[6];
    const float* W2     = (const float*)d_in[7];
    const float* b2     = (const float*)d_in[8];
    float* out = (float*)d_out;

    cudaFuncSetAttribute(attn_kernel, cudaFuncAttributeMaxDynamicSharedMemorySize,
                         ATTN_SMEM);

    queue_kernel<<<1, 1024>>>(inputs, out, out_size);
    xk_kernel<<<1250, 256>>>(emb, klstm, blstm);
    lstm_kernel<<<64, 128>>>(rklstm, inputs);
    attn_kernel<<<dim3(16, 64), 128, ATTN_SMEM>>>();
    combine_final<<<64, 256>>>(W1, b1, W2, b2, out);
}